// round 6
// baseline (speedup 1.0000x reference)
#include <cuda_runtime.h>
#include <cuda_bf16.h>
#include <cstdint>

// Problem constants
#define B_     32
#define IN_CH  16
#define OUT_CH 16
#define KK     3
#define DIL    4
#define COND   8
#define T_OUT  65536
#define PADW   (DIL * (KK - 1))      // 8
#define T_IN   (T_OUT + PADW)        // 65544
#define WSZ    (IN_CH * KK * OUT_CH) // 768

// Tile geometry: 64 tiles of 1024 timesteps per batch (512 pairs per tile).
#define TILE_T   1024
#define TILE_P   (TILE_T / 2)        // 512 pairs
#define ROW_P    516                 // pairs per channel row (512 + 4 tap pad)
#define ROW_PAD  520                 // smem row stride in u64 (16B aligned)
#define ROW_BYTES (ROW_P * 8)        // 4128, multiple of 16
#define CPS      2                   // channels per pipeline stage
#define NSTAGES  (IN_CH / CPS)       // 8
#define NBUF     3                   // triple buffer, issue depth 2

// Per-batch hypernet weights, duplicated as {w,w} in 64 bits so one shared
// load yields the packed B operand of fma.rn.f32x2.
__device__ ulonglong2 g_w[B_ * WSZ / 2];

// ---------------------------------------------------------------------------
// Kernel 1: hypernetwork.  grid=B_, block=WSZ threads.
// ---------------------------------------------------------------------------
__global__ void hyper_kernel(const float* __restrict__ p,
                             const float* __restrict__ W1,
                             const float* __restrict__ b1,
                             const float* __restrict__ W2,
                             const float* __restrict__ b2) {
    const int b = blockIdx.x;
    const int j = threadIdx.x;           // 0..767
    __shared__ float h[IN_CH];

    if (j < IN_CH) {
        float s = b1[j];
#pragma unroll
        for (int k = 0; k < COND; k++)
            s += p[b * COND + k] * W1[k * IN_CH + j];
        h[j] = (s > 0.0f) ? s : 0.2f * s;
    }
    __syncthreads();

    float s = b2[j];
#pragma unroll
    for (int c = 0; c < IN_CH; c++)
        s += h[c] * W2[c * WSZ + j];

    float2* w2out = reinterpret_cast<float2*>(g_w);
    w2out[b * WSZ + j] = make_float2(s, s);
}

// ---------------------------------------------------------------------------
// PTX helpers
// ---------------------------------------------------------------------------
__device__ __forceinline__ void fma2(unsigned long long& d,
                                     unsigned long long a,
                                     unsigned long long b) {
    asm volatile("fma.rn.f32x2 %0, %1, %2, %0;" : "+l"(d) : "l"(a), "l"(b));
}

__device__ __forceinline__ uint32_t smem_u32(const void* ptr) {
    uint32_t a;
    asm("{ .reg .u64 t; cvta.to.shared.u64 t, %1; cvt.u32.u64 %0, t; }"
        : "=r"(a) : "l"(ptr));
    return a;
}

__device__ __forceinline__ void mbar_init(uint32_t mbar, uint32_t count) {
    asm volatile("mbarrier.init.shared.b64 [%0], %1;" :: "r"(mbar), "r"(count)
                 : "memory");
}

__device__ __forceinline__ void mbar_expect_tx(uint32_t mbar, uint32_t bytes) {
    asm volatile("mbarrier.arrive.expect_tx.shared.b64 _, [%0], %1;"
                 :: "r"(mbar), "r"(bytes) : "memory");
}

__device__ __forceinline__ void bulk_g2s(uint32_t dst, const void* src,
                                         uint32_t bytes, uint32_t mbar) {
    asm volatile(
        "cp.async.bulk.shared::cta.global.mbarrier::complete_tx::bytes "
        "[%0], [%1], %2, [%3];"
        :: "r"(dst), "l"(src), "r"(bytes), "r"(mbar) : "memory");
}

__device__ __forceinline__ void mbar_wait(uint32_t mbar, uint32_t parity) {
    asm volatile(
        "{\n\t"
        ".reg .pred P;\n\t"
        "WAIT_%=:\n\t"
        "mbarrier.try_wait.parity.acquire.cta.shared::cta.b64 P, [%0], %1, 0x989680;\n\t"
        "@P bra.uni DONE_%=;\n\t"
        "bra.uni WAIT_%=;\n\t"
        "DONE_%=:\n\t"
        "}"
        :: "r"(mbar), "r"(parity) : "memory");
}

// ---------------------------------------------------------------------------
// Kernel 2: main conv, triple-buffered cp.async.bulk pipeline.
//   grid  = (64, 32), block = (128, 2), 3 CTAs/SM (24 warps).
//   tx -> 4 strided output pairs (stride 128), ty -> half of 16 out channels.
// Per-channel compute is tap-major to bound live registers:
//   per tap: 4x LDS.64 (x) + 4x LDS.128 broadcast (w) -> 32 packed FMAs.
// ---------------------------------------------------------------------------
__global__ __launch_bounds__(256, 3)
void conv_kernel(const float* __restrict__ x, float* __restrict__ y) {
    const int b   = blockIdx.y;
    const int tx  = threadIdx.x;                 // 0..127
    const int oh  = threadIdx.y;                 // 0..1
    const int tid = oh * 128 + tx;               // 0..255

    __shared__ __align__(16) unsigned long long xs[NBUF][CPS][ROW_PAD];
    __shared__ ulonglong2 ws[WSZ / 2];           // 6KB duplicated weights
    __shared__ __align__(8) unsigned long long mbar_store[NBUF];

    // Cooperative weight load (visible after the init __syncthreads).
#pragma unroll
    for (int k = tid; k < WSZ / 2; k += 256)
        ws[k] = g_w[b * (WSZ / 2) + k];

    const uint32_t mbar0 = smem_u32(&mbar_store[0]);
    if (tid == 0) {
#pragma unroll
        for (int i = 0; i < NBUF; i++)
            mbar_init(mbar0 + 8u * i, 1);
    }
    __syncthreads();

    // Per-channel gmem source rows for this tile.
    const float* xbase = x + (size_t)(b * IN_CH) * T_IN + blockIdx.x * TILE_T;

    // Prologue: issue stages 0 and 1.
    if (tid == 0) {
#pragma unroll
        for (int s = 0; s < 2; s++) {
            const uint32_t mb = mbar0 + 8u * s;
            mbar_expect_tx(mb, CPS * ROW_BYTES);
#pragma unroll
            for (int r = 0; r < CPS; r++)
                bulk_g2s(smem_u32(&xs[s][r][0]),
                         xbase + (size_t)(s * CPS + r) * T_IN, ROW_BYTES, mb);
        }
    }

    unsigned long long acc[4][8];                // [pair j][out ch in half]
#pragma unroll
    for (int j = 0; j < 4; j++)
#pragma unroll
        for (int op = 0; op < 8; op++)
            acc[j][op] = 0ULL;

#pragma unroll 1
    for (int s = 0; s < NSTAGES; s++) {
        const int buf = s % NBUF;
        mbar_wait(mbar0 + 8u * buf, (s / NBUF) & 1);
        __syncthreads();   // all threads done with stage s-1 -> buffer free

        if (s + 2 < NSTAGES && tid == 0) {
            const int t  = s + 2;
            const int tb = t % NBUF;
            const uint32_t mb = mbar0 + 8u * tb;
            mbar_expect_tx(mb, CPS * ROW_BYTES);
#pragma unroll
            for (int r = 0; r < CPS; r++)
                bulk_g2s(smem_u32(&xs[tb][r][0]),
                         xbase + (size_t)(t * CPS + r) * T_IN, ROW_BYTES, mb);
        }

#pragma unroll
        for (int cc = 0; cc < CPS; cc++) {
            const int c = s * CPS + cc;
            const unsigned long long* xr = &xs[buf][cc][tx];
            const ulonglong2* wrow = &ws[(c * OUT_CH + oh * 8) / 2];

            // Tap-major: bounded live set (4 xv + 1 w beyond accumulators).
#pragma unroll
            for (int i = 0; i < 3; i++) {
                unsigned long long xv0 = xr[0 * 128 + 4 - 2 * i];
                unsigned long long xv1 = xr[1 * 128 + 4 - 2 * i];
                unsigned long long xv2 = xr[2 * 128 + 4 - 2 * i];
                unsigned long long xv3 = xr[3 * 128 + 4 - 2 * i];

                const ulonglong2* wt = wrow + i * (IN_CH * OUT_CH / 2);
#pragma unroll
                for (int m = 0; m < 4; m++) {
                    const ulonglong2 w = wt[m];      // broadcast LDS.128
                    fma2(acc[0][2 * m + 0], xv0, w.x);
                    fma2(acc[0][2 * m + 1], xv0, w.y);
                    fma2(acc[1][2 * m + 0], xv1, w.x);
                    fma2(acc[1][2 * m + 1], xv1, w.y);
                    fma2(acc[2][2 * m + 0], xv2, w.x);
                    fma2(acc[2][2 * m + 1], xv2, w.y);
                    fma2(acc[3][2 * m + 0], xv3, w.x);
                    fma2(acc[3][2 * m + 1], xv3, w.y);
                }
            }
        }
    }

    // Store: y[b][oh*8+op][...], coalesced STG.64
    const int p0 = blockIdx.x * TILE_P + tx;
    unsigned long long* yb =
        reinterpret_cast<unsigned long long*>(y + (size_t)(b * OUT_CH + oh * 8) * T_OUT) + p0;
    const int yrowp = T_OUT / 2;
#pragma unroll
    for (int op = 0; op < 8; op++) {
        unsigned long long* yo = yb + op * yrowp;
#pragma unroll
        for (int j = 0; j < 4; j++)
            yo[128 * j] = acc[j][op];
    }
}

// ---------------------------------------------------------------------------
extern "C" void kernel_launch(void* const* d_in, const int* in_sizes, int n_in,
                              void* d_out, int out_size) {
    const float* x  = (const float*)d_in[0];
    const float* p  = (const float*)d_in[1];
    const float* W1 = (const float*)d_in[2];
    const float* b1 = (const float*)d_in[3];
    const float* W2 = (const float*)d_in[4];
    const float* b2 = (const float*)d_in[5];
    float* y = (float*)d_out;

    hyper_kernel<<<B_, WSZ>>>(p, W1, b1, W2, b2);

    dim3 grid(T_OUT / TILE_T, B_);
    dim3 block(128, 2);
    conv_kernel<<<grid, block>>>(x, y);
}

// round 7
// speedup vs baseline: 1.0023x; 1.0023x over previous
#include <cuda_runtime.h>
#include <cuda_bf16.h>
#include <cstdint>

// Problem constants
#define B_     32
#define IN_CH  16
#define OUT_CH 16
#define KK     3
#define DIL    4
#define COND   8
#define T_OUT  65536
#define PADW   (DIL * (KK - 1))      // 8
#define T_IN   (T_OUT + PADW)        // 65544
#define WSZ    (IN_CH * KK * OUT_CH) // 768

// Tile geometry: 64 tiles of 1024 timesteps per batch (512 pairs per tile).
#define TILE_T   1024
#define TILE_P   (TILE_T / 2)        // 512 pairs
#define ROW_P    516                 // pairs per channel row (512 + 4 tap pad)
#define ROW_PAD  520                 // smem row stride in u64 (16B aligned)
#define ROW_BYTES (ROW_P * 8)        // 4128, multiple of 16
#define CPS      2                   // channels per pipeline stage
#define NSTAGES  (IN_CH / CPS)       // 8
#define NBUF     3                   // triple buffer, issue depth 2

// Per-batch hypernet weights, duplicated as {w,w} in 64 bits so one shared
// load yields the packed B operand of fma.rn.f32x2.
__device__ ulonglong2 g_w[B_ * WSZ / 2];

// ---------------------------------------------------------------------------
// Kernel 1: hypernetwork.  grid=B_, block=WSZ threads.
// ---------------------------------------------------------------------------
__global__ void hyper_kernel(const float* __restrict__ p,
                             const float* __restrict__ W1,
                             const float* __restrict__ b1,
                             const float* __restrict__ W2,
                             const float* __restrict__ b2) {
    const int b = blockIdx.x;
    const int j = threadIdx.x;           // 0..767
    __shared__ float h[IN_CH];

    if (j < IN_CH) {
        float s = b1[j];
#pragma unroll
        for (int k = 0; k < COND; k++)
            s += p[b * COND + k] * W1[k * IN_CH + j];
        h[j] = (s > 0.0f) ? s : 0.2f * s;
    }
    __syncthreads();

    float s = b2[j];
#pragma unroll
    for (int c = 0; c < IN_CH; c++)
        s += h[c] * W2[c * WSZ + j];

    float2* w2out = reinterpret_cast<float2*>(g_w);
    w2out[b * WSZ + j] = make_float2(s, s);
}

// ---------------------------------------------------------------------------
// PTX helpers
// ---------------------------------------------------------------------------
__device__ __forceinline__ void fma2(unsigned long long& d,
                                     unsigned long long a,
                                     unsigned long long b) {
    asm volatile("fma.rn.f32x2 %0, %1, %2, %0;" : "+l"(d) : "l"(a), "l"(b));
}

__device__ __forceinline__ uint32_t smem_u32(const void* ptr) {
    uint32_t a;
    asm("{ .reg .u64 t; cvta.to.shared.u64 t, %1; cvt.u32.u64 %0, t; }"
        : "=r"(a) : "l"(ptr));
    return a;
}

__device__ __forceinline__ void mbar_init(uint32_t mbar, uint32_t count) {
    asm volatile("mbarrier.init.shared.b64 [%0], %1;" :: "r"(mbar), "r"(count)
                 : "memory");
}

__device__ __forceinline__ void mbar_expect_tx(uint32_t mbar, uint32_t bytes) {
    asm volatile("mbarrier.arrive.expect_tx.shared.b64 _, [%0], %1;"
                 :: "r"(mbar), "r"(bytes) : "memory");
}

__device__ __forceinline__ void bulk_g2s(uint32_t dst, const void* src,
                                         uint32_t bytes, uint32_t mbar) {
    asm volatile(
        "cp.async.bulk.shared::cta.global.mbarrier::complete_tx::bytes "
        "[%0], [%1], %2, [%3];"
        :: "r"(dst), "l"(src), "r"(bytes), "r"(mbar) : "memory");
}

__device__ __forceinline__ void mbar_wait(uint32_t mbar, uint32_t parity) {
    asm volatile(
        "{\n\t"
        ".reg .pred P;\n\t"
        "WAIT_%=:\n\t"
        "mbarrier.try_wait.parity.acquire.cta.shared::cta.b64 P, [%0], %1, 0x989680;\n\t"
        "@P bra.uni DONE_%=;\n\t"
        "bra.uni WAIT_%=;\n\t"
        "DONE_%=:\n\t"
        "}"
        :: "r"(mbar), "r"(parity) : "memory");
}

// ---------------------------------------------------------------------------
// Kernel 2: main conv, triple-buffered cp.async.bulk pipeline.
//   grid  = (64, 32), block = (128, 2), 3 CTAs/SM (24 warps).
//   tx -> 4 strided output pairs (stride 128), ty -> half of 16 out channels.
// Per-channel compute is tap-major to bound live registers:
//   per tap: 4x LDS.64 (x) + 4x LDS.128 broadcast (w) -> 32 packed FMAs.
// ---------------------------------------------------------------------------
__global__ __launch_bounds__(256, 3)
void conv_kernel(const float* __restrict__ x, float* __restrict__ y) {
    const int b   = blockIdx.y;
    const int tx  = threadIdx.x;                 // 0..127
    const int oh  = threadIdx.y;                 // 0..1
    const int tid = oh * 128 + tx;               // 0..255

    __shared__ __align__(16) unsigned long long xs[NBUF][CPS][ROW_PAD];
    __shared__ ulonglong2 ws[WSZ / 2];           // 6KB duplicated weights
    __shared__ __align__(8) unsigned long long mbar_store[NBUF];

    // Cooperative weight load (visible after the init __syncthreads).
#pragma unroll
    for (int k = tid; k < WSZ / 2; k += 256)
        ws[k] = g_w[b * (WSZ / 2) + k];

    const uint32_t mbar0 = smem_u32(&mbar_store[0]);
    if (tid == 0) {
#pragma unroll
        for (int i = 0; i < NBUF; i++)
            mbar_init(mbar0 + 8u * i, 1);
    }
    __syncthreads();

    // Per-channel gmem source rows for this tile.
    const float* xbase = x + (size_t)(b * IN_CH) * T_IN + blockIdx.x * TILE_T;

    // Prologue: issue stages 0 and 1.
    if (tid == 0) {
#pragma unroll
        for (int s = 0; s < 2; s++) {
            const uint32_t mb = mbar0 + 8u * s;
            mbar_expect_tx(mb, CPS * ROW_BYTES);
#pragma unroll
            for (int r = 0; r < CPS; r++)
                bulk_g2s(smem_u32(&xs[s][r][0]),
                         xbase + (size_t)(s * CPS + r) * T_IN, ROW_BYTES, mb);
        }
    }

    unsigned long long acc[4][8];                // [pair j][out ch in half]
#pragma unroll
    for (int j = 0; j < 4; j++)
#pragma unroll
        for (int op = 0; op < 8; op++)
            acc[j][op] = 0ULL;

#pragma unroll 1
    for (int s = 0; s < NSTAGES; s++) {
        const int buf = s % NBUF;
        mbar_wait(mbar0 + 8u * buf, (s / NBUF) & 1);
        __syncthreads();   // all threads done with stage s-1 -> buffer free

        if (s + 2 < NSTAGES && tid == 0) {
            const int t  = s + 2;
            const int tb = t % NBUF;
            const uint32_t mb = mbar0 + 8u * tb;
            mbar_expect_tx(mb, CPS * ROW_BYTES);
#pragma unroll
            for (int r = 0; r < CPS; r++)
                bulk_g2s(smem_u32(&xs[tb][r][0]),
                         xbase + (size_t)(t * CPS + r) * T_IN, ROW_BYTES, mb);
        }

#pragma unroll
        for (int cc = 0; cc < CPS; cc++) {
            const int c = s * CPS + cc;
            const unsigned long long* xr = &xs[buf][cc][tx];
            const ulonglong2* wrow = &ws[(c * OUT_CH + oh * 8) / 2];

            // Tap-major: bounded live set (4 xv + 1 w beyond accumulators).
#pragma unroll
            for (int i = 0; i < 3; i++) {
                unsigned long long xv0 = xr[0 * 128 + 4 - 2 * i];
                unsigned long long xv1 = xr[1 * 128 + 4 - 2 * i];
                unsigned long long xv2 = xr[2 * 128 + 4 - 2 * i];
                unsigned long long xv3 = xr[3 * 128 + 4 - 2 * i];

                const ulonglong2* wt = wrow + i * (IN_CH * OUT_CH / 2);
#pragma unroll
                for (int m = 0; m < 4; m++) {
                    const ulonglong2 w = wt[m];      // broadcast LDS.128
                    fma2(acc[0][2 * m + 0], xv0, w.x);
                    fma2(acc[0][2 * m + 1], xv0, w.y);
                    fma2(acc[1][2 * m + 0], xv1, w.x);
                    fma2(acc[1][2 * m + 1], xv1, w.y);
                    fma2(acc[2][2 * m + 0], xv2, w.x);
                    fma2(acc[2][2 * m + 1], xv2, w.y);
                    fma2(acc[3][2 * m + 0], xv3, w.x);
                    fma2(acc[3][2 * m + 1], xv3, w.y);
                }
            }
        }
    }

    // Store: y[b][oh*8+op][...], coalesced STG.64
    const int p0 = blockIdx.x * TILE_P + tx;
    unsigned long long* yb =
        reinterpret_cast<unsigned long long*>(y + (size_t)(b * OUT_CH + oh * 8) * T_OUT) + p0;
    const int yrowp = T_OUT / 2;
#pragma unroll
    for (int op = 0; op < 8; op++) {
        unsigned long long* yo = yb + op * yrowp;
#pragma unroll
        for (int j = 0; j < 4; j++)
            yo[128 * j] = acc[j][op];
    }
}

// ---------------------------------------------------------------------------
extern "C" void kernel_launch(void* const* d_in, const int* in_sizes, int n_in,
                              void* d_out, int out_size) {
    const float* x  = (const float*)d_in[0];
    const float* p  = (const float*)d_in[1];
    const float* W1 = (const float*)d_in[2];
    const float* b1 = (const float*)d_in[3];
    const float* W2 = (const float*)d_in[4];
    const float* b2 = (const float*)d_in[5];
    float* y = (float*)d_out;

    hyper_kernel<<<B_, WSZ>>>(p, W1, b1, W2, b2);

    dim3 grid(T_OUT / TILE_T, B_);
    dim3 block(128, 2);
    conv_kernel<<<grid, block>>>(x, y);
}

// round 8
// speedup vs baseline: 1.0064x; 1.0042x over previous
#include <cuda_runtime.h>
#include <cuda_bf16.h>
#include <cstdint>

// Problem constants
#define B_     32
#define IN_CH  16
#define OUT_CH 16
#define KK     3
#define DIL    4
#define COND   8
#define T_OUT  65536
#define PADW   (DIL * (KK - 1))      // 8
#define T_IN   (T_OUT + PADW)        // 65544
#define WSZ    (IN_CH * KK * OUT_CH) // 768

// Tile geometry: 64 tiles of 1024 timesteps per batch (512 pairs per tile).
#define TILE_T   1024
#define TILE_P   (TILE_T / 2)        // 512 pairs
#define ROW_P    516                 // pairs per channel row (512 + 4 tap pad)
#define ROW_PAD  520                 // smem row stride in u64 (16B aligned)
#define ROW_BYTES (ROW_P * 8)        // 4128, multiple of 16
#define CPS      2                   // channels per pipeline stage
#define NSTAGES  (IN_CH / CPS)       // 8
#define NBUF     3                   // triple buffer, issue depth 2

// Per-batch hypernet weights, duplicated as {w,w} in 64 bits so one shared
// load yields the packed B operand of fma.rn.f32x2.
__device__ ulonglong2 g_w[B_ * WSZ / 2];

// ---------------------------------------------------------------------------
// Kernel 1: hypernetwork.  grid=B_, block=WSZ threads.
// ---------------------------------------------------------------------------
__global__ void hyper_kernel(const float* __restrict__ p,
                             const float* __restrict__ W1,
                             const float* __restrict__ b1,
                             const float* __restrict__ W2,
                             const float* __restrict__ b2) {
    const int b = blockIdx.x;
    const int j = threadIdx.x;           // 0..767
    __shared__ float h[IN_CH];

    if (j < IN_CH) {
        float s = b1[j];
#pragma unroll
        for (int k = 0; k < COND; k++)
            s += p[b * COND + k] * W1[k * IN_CH + j];
        h[j] = (s > 0.0f) ? s : 0.2f * s;
    }
    __syncthreads();

    float s = b2[j];
#pragma unroll
    for (int c = 0; c < IN_CH; c++)
        s += h[c] * W2[c * WSZ + j];

    float2* w2out = reinterpret_cast<float2*>(g_w);
    w2out[b * WSZ + j] = make_float2(s, s);
}

// ---------------------------------------------------------------------------
// PTX helpers
// ---------------------------------------------------------------------------
__device__ __forceinline__ void fma2(unsigned long long& d,
                                     unsigned long long a,
                                     unsigned long long b) {
    asm volatile("fma.rn.f32x2 %0, %1, %2, %0;" : "+l"(d) : "l"(a), "l"(b));
}

__device__ __forceinline__ uint32_t smem_u32(const void* ptr) {
    uint32_t a;
    asm("{ .reg .u64 t; cvta.to.shared.u64 t, %1; cvt.u32.u64 %0, t; }"
        : "=r"(a) : "l"(ptr));
    return a;
}

__device__ __forceinline__ void mbar_init(uint32_t mbar, uint32_t count) {
    asm volatile("mbarrier.init.shared.b64 [%0], %1;" :: "r"(mbar), "r"(count)
                 : "memory");
}

__device__ __forceinline__ void mbar_expect_tx(uint32_t mbar, uint32_t bytes) {
    asm volatile("mbarrier.arrive.expect_tx.shared.b64 _, [%0], %1;"
                 :: "r"(mbar), "r"(bytes) : "memory");
}

__device__ __forceinline__ void bulk_g2s(uint32_t dst, const void* src,
                                         uint32_t bytes, uint32_t mbar) {
    asm volatile(
        "cp.async.bulk.shared::cta.global.mbarrier::complete_tx::bytes "
        "[%0], [%1], %2, [%3];"
        :: "r"(dst), "l"(src), "r"(bytes), "r"(mbar) : "memory");
}

__device__ __forceinline__ void mbar_wait(uint32_t mbar, uint32_t parity) {
    asm volatile(
        "{\n\t"
        ".reg .pred P;\n\t"
        "WAIT_%=:\n\t"
        "mbarrier.try_wait.parity.acquire.cta.shared::cta.b64 P, [%0], %1, 0x989680;\n\t"
        "@P bra.uni DONE_%=;\n\t"
        "bra.uni WAIT_%=;\n\t"
        "DONE_%=:\n\t"
        "}"
        :: "r"(mbar), "r"(parity) : "memory");
}

// ---------------------------------------------------------------------------
// Kernel 2: main conv, triple-buffered cp.async.bulk pipeline.
//   grid  = (64, 32), block = (128, 2), 3 CTAs/SM (24 warps).
//   tx -> 4 strided output pairs (stride 128), ty -> half of 16 out channels.
// Per-channel compute is tap-major to bound live registers:
//   per tap: 4x LDS.64 (x) + 4x LDS.128 broadcast (w) -> 32 packed FMAs.
// ---------------------------------------------------------------------------
__global__ __launch_bounds__(256, 3)
void conv_kernel(const float* __restrict__ x, float* __restrict__ y) {
    const int b   = blockIdx.y;
    const int tx  = threadIdx.x;                 // 0..127
    const int oh  = threadIdx.y;                 // 0..1
    const int tid = oh * 128 + tx;               // 0..255

    __shared__ __align__(16) unsigned long long xs[NBUF][CPS][ROW_PAD];
    __shared__ ulonglong2 ws[WSZ / 2];           // 6KB duplicated weights
    __shared__ __align__(8) unsigned long long mbar_store[NBUF];

    // Cooperative weight load (visible after the init __syncthreads).
#pragma unroll
    for (int k = tid; k < WSZ / 2; k += 256)
        ws[k] = g_w[b * (WSZ / 2) + k];

    const uint32_t mbar0 = smem_u32(&mbar_store[0]);
    if (tid == 0) {
#pragma unroll
        for (int i = 0; i < NBUF; i++)
            mbar_init(mbar0 + 8u * i, 1);
    }
    __syncthreads();

    // Per-channel gmem source rows for this tile.
    const float* xbase = x + (size_t)(b * IN_CH) * T_IN + blockIdx.x * TILE_T;

    // Prologue: issue stages 0 and 1.
    if (tid == 0) {
#pragma unroll
        for (int s = 0; s < 2; s++) {
            const uint32_t mb = mbar0 + 8u * s;
            mbar_expect_tx(mb, CPS * ROW_BYTES);
#pragma unroll
            for (int r = 0; r < CPS; r++)
                bulk_g2s(smem_u32(&xs[s][r][0]),
                         xbase + (size_t)(s * CPS + r) * T_IN, ROW_BYTES, mb);
        }
    }

    unsigned long long acc[4][8];                // [pair j][out ch in half]
#pragma unroll
    for (int j = 0; j < 4; j++)
#pragma unroll
        for (int op = 0; op < 8; op++)
            acc[j][op] = 0ULL;

#pragma unroll 1
    for (int s = 0; s < NSTAGES; s++) {
        const int buf = s % NBUF;
        mbar_wait(mbar0 + 8u * buf, (s / NBUF) & 1);
        __syncthreads();   // all threads done with stage s-1 -> buffer free

        if (s + 2 < NSTAGES && tid == 0) {
            const int t  = s + 2;
            const int tb = t % NBUF;
            const uint32_t mb = mbar0 + 8u * tb;
            mbar_expect_tx(mb, CPS * ROW_BYTES);
#pragma unroll
            for (int r = 0; r < CPS; r++)
                bulk_g2s(smem_u32(&xs[tb][r][0]),
                         xbase + (size_t)(t * CPS + r) * T_IN, ROW_BYTES, mb);
        }

#pragma unroll
        for (int cc = 0; cc < CPS; cc++) {
            const int c = s * CPS + cc;
            const unsigned long long* xr = &xs[buf][cc][tx];
            const ulonglong2* wrow = &ws[(c * OUT_CH + oh * 8) / 2];

            // Tap-major: bounded live set (4 xv + 1 w beyond accumulators).
#pragma unroll
            for (int i = 0; i < 3; i++) {
                unsigned long long xv0 = xr[0 * 128 + 4 - 2 * i];
                unsigned long long xv1 = xr[1 * 128 + 4 - 2 * i];
                unsigned long long xv2 = xr[2 * 128 + 4 - 2 * i];
                unsigned long long xv3 = xr[3 * 128 + 4 - 2 * i];

                const ulonglong2* wt = wrow + i * (IN_CH * OUT_CH / 2);
#pragma unroll
                for (int m = 0; m < 4; m++) {
                    const ulonglong2 w = wt[m];      // broadcast LDS.128
                    fma2(acc[0][2 * m + 0], xv0, w.x);
                    fma2(acc[0][2 * m + 1], xv0, w.y);
                    fma2(acc[1][2 * m + 0], xv1, w.x);
                    fma2(acc[1][2 * m + 1], xv1, w.y);
                    fma2(acc[2][2 * m + 0], xv2, w.x);
                    fma2(acc[2][2 * m + 1], xv2, w.y);
                    fma2(acc[3][2 * m + 0], xv3, w.x);
                    fma2(acc[3][2 * m + 1], xv3, w.y);
                }
            }
        }
    }

    // Store: y[b][oh*8+op][...], coalesced STG.64
    const int p0 = blockIdx.x * TILE_P + tx;
    unsigned long long* yb =
        reinterpret_cast<unsigned long long*>(y + (size_t)(b * OUT_CH + oh * 8) * T_OUT) + p0;
    const int yrowp = T_OUT / 2;
#pragma unroll
    for (int op = 0; op < 8; op++) {
        unsigned long long* yo = yb + op * yrowp;
#pragma unroll
        for (int j = 0; j < 4; j++)
            yo[128 * j] = acc[j][op];
    }
}

// ---------------------------------------------------------------------------
extern "C" void kernel_launch(void* const* d_in, const int* in_sizes, int n_in,
                              void* d_out, int out_size) {
    const float* x  = (const float*)d_in[0];
    const float* p  = (const float*)d_in[1];
    const float* W1 = (const float*)d_in[2];
    const float* b1 = (const float*)d_in[3];
    const float* W2 = (const float*)d_in[4];
    const float* b2 = (const float*)d_in[5];
    float* y = (float*)d_out;

    hyper_kernel<<<B_, WSZ>>>(p, W1, b1, W2, b2);

    dim3 grid(T_OUT / TILE_T, B_);
    dim3 block(128, 2);
    conv_kernel<<<grid, block>>>(x, y);
}

// round 9
// speedup vs baseline: 1.8450x; 1.8331x over previous
#include <cuda_runtime.h>
#include <cuda_bf16.h>
#include <cstdint>

// Problem constants
#define B_     32
#define IN_CH  16
#define OUT_CH 16
#define KK     3
#define DIL    4
#define COND   8
#define T_OUT  65536
#define PADW   (DIL * (KK - 1))      // 8
#define T_IN   (T_OUT + PADW)        // 65544
#define WSZ    (IN_CH * KK * OUT_CH) // 768

// Tile geometry: 64 tiles of 1024 timesteps per batch (512 pairs per tile).
#define TILE_T   1024
#define TILE_P   (TILE_T / 2)        // 512 pairs
#define ROW_P    516                 // pairs per channel row (512 + 4 tap pad)
#define ROW_PAD  520                 // smem row stride in u64 (16B aligned)
#define ROW_BYTES (ROW_P * 8)        // 4128, multiple of 16
#define CPS      4                   // channels per pipeline stage
#define NSTAGES  (IN_CH / CPS)       // 4
#define NBUF     3                   // triple buffer, issue depth 2 (8 ch ahead)

// Per-batch hypernet weights, duplicated as {w,w} in 64 bits so one shared
// load yields the packed B operand of fma.rn.f32x2.
__device__ ulonglong2 g_w[B_ * WSZ / 2];

// ---------------------------------------------------------------------------
// Kernel 1: hypernetwork.  grid=B_, block=WSZ threads.
// ---------------------------------------------------------------------------
__global__ void hyper_kernel(const float* __restrict__ p,
                             const float* __restrict__ W1,
                             const float* __restrict__ b1,
                             const float* __restrict__ W2,
                             const float* __restrict__ b2) {
    const int b = blockIdx.x;
    const int j = threadIdx.x;           // 0..767
    __shared__ float h[IN_CH];

    if (j < IN_CH) {
        float s = b1[j];
#pragma unroll
        for (int k = 0; k < COND; k++)
            s += p[b * COND + k] * W1[k * IN_CH + j];
        h[j] = (s > 0.0f) ? s : 0.2f * s;
    }
    __syncthreads();

    float s = b2[j];
#pragma unroll
    for (int c = 0; c < IN_CH; c++)
        s += h[c] * W2[c * WSZ + j];

    float2* w2out = reinterpret_cast<float2*>(g_w);
    w2out[b * WSZ + j] = make_float2(s, s);
}

// ---------------------------------------------------------------------------
// PTX helpers
// ---------------------------------------------------------------------------
__device__ __forceinline__ void fma2(unsigned long long& d,
                                     unsigned long long a,
                                     unsigned long long b) {
    asm volatile("fma.rn.f32x2 %0, %1, %2, %0;" : "+l"(d) : "l"(a), "l"(b));
}

__device__ __forceinline__ uint32_t smem_u32(const void* ptr) {
    uint32_t a;
    asm("{ .reg .u64 t; cvta.to.shared.u64 t, %1; cvt.u32.u64 %0, t; }"
        : "=r"(a) : "l"(ptr));
    return a;
}

__device__ __forceinline__ void mbar_init(uint32_t mbar, uint32_t count) {
    asm volatile("mbarrier.init.shared.b64 [%0], %1;" :: "r"(mbar), "r"(count)
                 : "memory");
}

__device__ __forceinline__ void mbar_expect_tx(uint32_t mbar, uint32_t bytes) {
    asm volatile("mbarrier.arrive.expect_tx.shared.b64 _, [%0], %1;"
                 :: "r"(mbar), "r"(bytes) : "memory");
}

__device__ __forceinline__ void bulk_g2s(uint32_t dst, const void* src,
                                         uint32_t bytes, uint32_t mbar) {
    asm volatile(
        "cp.async.bulk.shared::cta.global.mbarrier::complete_tx::bytes "
        "[%0], [%1], %2, [%3];"
        :: "r"(dst), "l"(src), "r"(bytes), "r"(mbar) : "memory");
}

__device__ __forceinline__ void mbar_wait(uint32_t mbar, uint32_t parity) {
    asm volatile(
        "{\n\t"
        ".reg .pred P;\n\t"
        "WAIT_%=:\n\t"
        "mbarrier.try_wait.parity.acquire.cta.shared::cta.b64 P, [%0], %1, 0x989680;\n\t"
        "@P bra.uni DONE_%=;\n\t"
        "bra.uni WAIT_%=;\n\t"
        "DONE_%=:\n\t"
        "}"
        :: "r"(mbar), "r"(parity) : "memory");
}

// ---------------------------------------------------------------------------
// Kernel 2: main conv, triple-buffered cp.async.bulk pipeline.
//   grid  = (64, 32), block = (128, 2), 2 CTAs/SM (R3's proven geometry).
//   tx -> 4 strided output pairs (stride 128), ty -> half of 16 out channels.
// CPS=4: only 4 stage boundaries per tile; prefetch runs 8 channels ahead.
// ---------------------------------------------------------------------------
__global__ __launch_bounds__(256, 2)
void conv_kernel(const float* __restrict__ x, float* __restrict__ y) {
    const int b   = blockIdx.y;
    const int tx  = threadIdx.x;                 // 0..127
    const int oh  = threadIdx.y;                 // 0..1
    const int tid = oh * 128 + tx;               // 0..255

    __shared__ __align__(16) unsigned long long xs[NBUF][CPS][ROW_PAD];
    __shared__ ulonglong2 ws[WSZ / 2];           // 6KB duplicated weights
    __shared__ __align__(8) unsigned long long mbar_store[NBUF];

    // Cooperative weight load (visible after the init __syncthreads).
#pragma unroll
    for (int k = tid; k < WSZ / 2; k += 256)
        ws[k] = g_w[b * (WSZ / 2) + k];

    const uint32_t mbar0 = smem_u32(&mbar_store[0]);
    if (tid == 0) {
#pragma unroll
        for (int i = 0; i < NBUF; i++)
            mbar_init(mbar0 + 8u * i, 1);
    }
    __syncthreads();

    // Per-channel gmem source rows for this tile.
    const float* xbase = x + (size_t)(b * IN_CH) * T_IN + blockIdx.x * TILE_T;

    // Prologue: issue stages 0 and 1 (channels 0..7).
    if (tid == 0) {
#pragma unroll
        for (int s = 0; s < 2; s++) {
            const uint32_t mb = mbar0 + 8u * s;
            mbar_expect_tx(mb, CPS * ROW_BYTES);
#pragma unroll
            for (int r = 0; r < CPS; r++)
                bulk_g2s(smem_u32(&xs[s][r][0]),
                         xbase + (size_t)(s * CPS + r) * T_IN, ROW_BYTES, mb);
        }
    }

    unsigned long long acc[4][8];                // [pair j][out ch in half]
#pragma unroll
    for (int j = 0; j < 4; j++)
#pragma unroll
        for (int op = 0; op < 8; op++)
            acc[j][op] = 0ULL;

#pragma unroll 1
    for (int s = 0; s < NSTAGES; s++) {
        const int buf = s % NBUF;
        mbar_wait(mbar0 + 8u * buf, (s / NBUF) & 1);
        __syncthreads();   // all threads done with stage s-1 -> buffer free

        if (s + 2 < NSTAGES && tid == 0) {
            const int t  = s + 2;
            const int tb = t % NBUF;
            const uint32_t mb = mbar0 + 8u * tb;
            mbar_expect_tx(mb, CPS * ROW_BYTES);
#pragma unroll
            for (int r = 0; r < CPS; r++)
                bulk_g2s(smem_u32(&xs[tb][r][0]),
                         xbase + (size_t)(t * CPS + r) * T_IN, ROW_BYTES, mb);
        }

#pragma unroll
        for (int cc = 0; cc < CPS; cc++) {
            const int c = s * CPS + cc;
            const unsigned long long* xr = &xs[buf][cc][tx];

            // 12 conflict-free LDS.64: tap i at pair offset (4 - 2i)
            unsigned long long xv[4][3];
#pragma unroll
            for (int j = 0; j < 4; j++)
#pragma unroll
                for (int i = 0; i < 3; i++)
                    xv[j][i] = xr[128 * j + 4 - 2 * i];

            const ulonglong2* wrow = &ws[(c * OUT_CH + oh * 8) / 2];
#pragma unroll
            for (int i = 0; i < 3; i++) {
                const ulonglong2* wt = wrow + i * (IN_CH * OUT_CH / 2);
#pragma unroll
                for (int m = 0; m < 4; m++) {
                    const ulonglong2 w = wt[m];      // broadcast LDS.128
#pragma unroll
                    for (int j = 0; j < 4; j++) {
                        fma2(acc[j][2 * m + 0], xv[j][i], w.x);
                        fma2(acc[j][2 * m + 1], xv[j][i], w.y);
                    }
                }
            }
        }
    }

    // Store: y[b][oh*8+op][...], coalesced STG.64
    const int p0 = blockIdx.x * TILE_P + tx;
    unsigned long long* yb =
        reinterpret_cast<unsigned long long*>(y + (size_t)(b * OUT_CH + oh * 8) * T_OUT) + p0;
    const int yrowp = T_OUT / 2;
#pragma unroll
    for (int op = 0; op < 8; op++) {
        unsigned long long* yo = yb + op * yrowp;
#pragma unroll
        for (int j = 0; j < 4; j++)
            yo[128 * j] = acc[j][op];
    }
}

// ---------------------------------------------------------------------------
extern "C" void kernel_launch(void* const* d_in, const int* in_sizes, int n_in,
                              void* d_out, int out_size) {
    const float* x  = (const float*)d_in[0];
    const float* p  = (const float*)d_in[1];
    const float* W1 = (const float*)d_in[2];
    const float* b1 = (const float*)d_in[3];
    const float* W2 = (const float*)d_in[4];
    const float* b2 = (const float*)d_in[5];
    float* y = (float*)d_out;

    hyper_kernel<<<B_, WSZ>>>(p, W1, b1, W2, b2);

    dim3 grid(T_OUT / TILE_T, B_);
    dim3 block(128, 2);
    conv_kernel<<<grid, block>>>(x, y);
}

// round 10
// speedup vs baseline: 1.9560x; 1.0602x over previous
#include <cuda_runtime.h>
#include <cuda_bf16.h>
#include <cstdint>

// Problem constants
#define B_     32
#define IN_CH  16
#define OUT_CH 16
#define KK     3
#define DIL    4
#define COND   8
#define T_OUT  65536
#define PADW   (DIL * (KK - 1))      // 8
#define T_IN   (T_OUT + PADW)        // 65544
#define WSZ    (IN_CH * KK * OUT_CH) // 768

// Tile geometry: 64 tiles of 1024 timesteps per batch (512 pairs per tile).
#define TILE_T   1024
#define TILE_P   (TILE_T / 2)        // 512 pairs
#define ROW_P    516                 // pairs per channel row (512 + 4 tap pad)
#define ROW_BYTES (ROW_P * 8)        // 4128, multiple of 16
#define CPS      2                   // channels per mbarrier group
#define NST      8                   // 8 groups, all resident (no buffer reuse)

// Per-batch hypernet weights, duplicated as {w,w} in 64 bits so one shared
// load yields the packed B operand of fma.rn.f32x2.
__device__ ulonglong2 g_w[B_ * WSZ / 2];

// ---------------------------------------------------------------------------
// Kernel 1: hypernetwork.  grid=B_, block=WSZ threads.
// ---------------------------------------------------------------------------
__global__ void hyper_kernel(const float* __restrict__ p,
                             const float* __restrict__ W1,
                             const float* __restrict__ b1,
                             const float* __restrict__ W2,
                             const float* __restrict__ b2) {
    const int b = blockIdx.x;
    const int j = threadIdx.x;           // 0..767
    __shared__ float h[IN_CH];

    if (j < IN_CH) {
        float s = b1[j];
#pragma unroll
        for (int k = 0; k < COND; k++)
            s += p[b * COND + k] * W1[k * IN_CH + j];
        h[j] = (s > 0.0f) ? s : 0.2f * s;
    }
    __syncthreads();

    float s = b2[j];
#pragma unroll
    for (int c = 0; c < IN_CH; c++)
        s += h[c] * W2[c * WSZ + j];

    float2* w2out = reinterpret_cast<float2*>(g_w);
    w2out[b * WSZ + j] = make_float2(s, s);
}

// ---------------------------------------------------------------------------
// PTX helpers
// ---------------------------------------------------------------------------
__device__ __forceinline__ void fma2(unsigned long long& d,
                                     unsigned long long a,
                                     unsigned long long b) {
    asm volatile("fma.rn.f32x2 %0, %1, %2, %0;" : "+l"(d) : "l"(a), "l"(b));
}

__device__ __forceinline__ uint32_t smem_u32(const void* ptr) {
    uint32_t a;
    asm("{ .reg .u64 t; cvta.to.shared.u64 t, %1; cvt.u32.u64 %0, t; }"
        : "=r"(a) : "l"(ptr));
    return a;
}

__device__ __forceinline__ void mbar_init(uint32_t mbar, uint32_t count) {
    asm volatile("mbarrier.init.shared.b64 [%0], %1;" :: "r"(mbar), "r"(count)
                 : "memory");
}

__device__ __forceinline__ void mbar_expect_tx(uint32_t mbar, uint32_t bytes) {
    asm volatile("mbarrier.arrive.expect_tx.shared.b64 _, [%0], %1;"
                 :: "r"(mbar), "r"(bytes) : "memory");
}

__device__ __forceinline__ void bulk_g2s(uint32_t dst, const void* src,
                                         uint32_t bytes, uint32_t mbar) {
    asm volatile(
        "cp.async.bulk.shared::cta.global.mbarrier::complete_tx::bytes "
        "[%0], [%1], %2, [%3];"
        :: "r"(dst), "l"(src), "r"(bytes), "r"(mbar) : "memory");
}

__device__ __forceinline__ void mbar_wait(uint32_t mbar, uint32_t parity) {
    asm volatile(
        "{\n\t"
        ".reg .pred P;\n\t"
        "WAIT_%=:\n\t"
        "mbarrier.try_wait.parity.acquire.cta.shared::cta.b64 P, [%0], %1, 0x989680;\n\t"
        "@P bra.uni DONE_%=;\n\t"
        "bra.uni WAIT_%=;\n\t"
        "DONE_%=:\n\t"
        "}"
        :: "r"(mbar), "r"(parity) : "memory");
}

// ---------------------------------------------------------------------------
// Kernel 2: main conv. All 16 channel rows staged upfront via cp.async.bulk
// into resident smem (no buffer reuse); main loop has NO block syncs — each
// warp flows through per-group mbarrier waits at its own pace.
//   grid  = (64, 32), block = (128, 2), 2 CTAs/SM.
//   tx -> output pairs {2tx, 2tx+1} and {256+2tx, 256+2tx+1}
//   ty -> half of 16 output channels.
// x tap operands per group = 3 contiguous LDS.128; weights broadcast LDS.128.
// ---------------------------------------------------------------------------
__global__ __launch_bounds__(256, 2)
void conv_kernel(const float* __restrict__ x, float* __restrict__ y) {
    const int b   = blockIdx.y;
    const int tx  = threadIdx.x;                 // 0..127
    const int oh  = threadIdx.y;                 // 0..1
    const int tid = oh * 128 + tx;               // 0..255

    __shared__ __align__(16) unsigned long long xs[NST][CPS][ROW_P];
    __shared__ ulonglong2 ws[WSZ / 2];           // 6KB duplicated weights
    __shared__ __align__(8) unsigned long long mbar_store[NST];

    // Cooperative weight load (visible after the init __syncthreads).
#pragma unroll
    for (int k = tid; k < WSZ / 2; k += 256)
        ws[k] = g_w[b * (WSZ / 2) + k];

    const uint32_t mbar0 = smem_u32(&mbar_store[0]);
    if (tid == 0) {
#pragma unroll
        for (int i = 0; i < NST; i++)
            mbar_init(mbar0 + 8u * i, 1);
    }
    __syncthreads();

    // Issue ALL channel-row copies upfront, 2 channels per mbarrier.
    const float* xbase = x + (size_t)(b * IN_CH) * T_IN + blockIdx.x * TILE_T;
    if (tid == 0) {
#pragma unroll
        for (int s = 0; s < NST; s++) {
            const uint32_t mb = mbar0 + 8u * s;
            mbar_expect_tx(mb, CPS * ROW_BYTES);
#pragma unroll
            for (int r = 0; r < CPS; r++)
                bulk_g2s(smem_u32(&xs[s][r][0]),
                         xbase + (size_t)(s * CPS + r) * T_IN, ROW_BYTES, mb);
        }
    }

    // acc[g][pp][op]: 2 groups x 2 consecutive pairs x 8 outs
    unsigned long long acc[2][2][8];
#pragma unroll
    for (int g = 0; g < 2; g++)
#pragma unroll
        for (int pp = 0; pp < 2; pp++)
#pragma unroll
            for (int op = 0; op < 8; op++)
                acc[g][pp][op] = 0ULL;

    const int q0 = 2 * tx;                       // first pair of group 0

#pragma unroll 1
    for (int s = 0; s < NST; s++) {
        mbar_wait(mbar0 + 8u * s, 0);            // per-warp, parity 0, once

#pragma unroll
        for (int cc = 0; cc < CPS; cc++) {
            const int c = s * CPS + cc;

            // x tap operands: groups g at pairs q0+256g; taps need u64
            // [q .. q+5] = 3 contiguous ulonglong2 (conflict-free LDS.128).
            const ulonglong2* xr2 =
                reinterpret_cast<const ulonglong2*>(&xs[s][cc][0]);
            ulonglong2 v[2][3];
#pragma unroll
            for (int g = 0; g < 2; g++)
#pragma unroll
                for (int k = 0; k < 3; k++)
                    v[g][k] = xr2[(q0 + 256 * g) / 2 + k];

            const ulonglong2* wrow = &ws[(c * OUT_CH + oh * 8) / 2];
            // tap i uses v[g][2-i]: .x for pair pp=0, .y for pp=1
#pragma unroll
            for (int i = 0; i < 3; i++) {
                const ulonglong2* wt = wrow + i * (IN_CH * OUT_CH / 2);
#pragma unroll
                for (int m = 0; m < 4; m++) {
                    const ulonglong2 w = wt[m];      // broadcast LDS.128
#pragma unroll
                    for (int g = 0; g < 2; g++) {
                        fma2(acc[g][0][2 * m + 0], v[g][2 - i].x, w.x);
                        fma2(acc[g][0][2 * m + 1], v[g][2 - i].x, w.y);
                        fma2(acc[g][1][2 * m + 0], v[g][2 - i].y, w.x);
                        fma2(acc[g][1][2 * m + 1], v[g][2 - i].y, w.y);
                    }
                }
            }
        }
    }

    // Store: y[b][oh*8+op][...] — one STG.128 per (op, group), coalesced.
    const int pbase = blockIdx.x * TILE_P + q0;  // global pair index, even
    float* ybase = y + (size_t)(b * OUT_CH + oh * 8) * T_OUT;
#pragma unroll
    for (int op = 0; op < 8; op++) {
        ulonglong2* yo = reinterpret_cast<ulonglong2*>(
            ybase + (size_t)op * T_OUT + 2 * pbase);
#pragma unroll
        for (int g = 0; g < 2; g++) {
            ulonglong2 out;
            out.x = acc[g][0][op];
            out.y = acc[g][1][op];
            yo[g * 128] = out;                   // +256 pairs = +128 u64x2
        }
    }
}

// ---------------------------------------------------------------------------
extern "C" void kernel_launch(void* const* d_in, const int* in_sizes, int n_in,
                              void* d_out, int out_size) {
    const float* x  = (const float*)d_in[0];
    const float* p  = (const float*)d_in[1];
    const float* W1 = (const float*)d_in[2];
    const float* b1 = (const float*)d_in[3];
    const float* W2 = (const float*)d_in[4];
    const float* b2 = (const float*)d_in[5];
    float* y = (float*)d_out;

    hyper_kernel<<<B_, WSZ>>>(p, W1, b1, W2, b2);

    dim3 grid(T_OUT / TILE_T, B_);
    dim3 block(128, 2);
    conv_kernel<<<grid, block>>>(x, y);
}

// round 11
// speedup vs baseline: 1.9897x; 1.0173x over previous
#include <cuda_runtime.h>
#include <cuda_bf16.h>
#include <cstdint>

// Problem constants
#define B_     32
#define IN_CH  16
#define OUT_CH 16
#define KK     3
#define DIL    4
#define COND   8
#define T_OUT  65536
#define PADW   (DIL * (KK - 1))      // 8
#define T_IN   (T_OUT + PADW)        // 65544
#define WSZ    (IN_CH * KK * OUT_CH) // 768

// Tile geometry: 64 tiles of 1024 timesteps per batch (512 pairs per tile).
#define TILE_T   1024
#define TILE_P   (TILE_T / 2)        // 512 pairs
#define ROW_P    516                 // pairs per channel row (512 + 4 tap pad)
#define ROW_BYTES (ROW_P * 8)        // 4128, multiple of 16
#define CPS      2                   // channels per mbarrier group
#define NST      8                   // 8 groups, all resident (no reuse)

// ---------------------------------------------------------------------------
// PTX helpers
// ---------------------------------------------------------------------------
__device__ __forceinline__ void fma2(unsigned long long& d,
                                     unsigned long long a,
                                     unsigned long long b) {
    asm volatile("fma.rn.f32x2 %0, %1, %2, %0;" : "+l"(d) : "l"(a), "l"(b));
}

__device__ __forceinline__ uint32_t smem_u32(const void* ptr) {
    uint32_t a;
    asm("{ .reg .u64 t; cvta.to.shared.u64 t, %1; cvt.u32.u64 %0, t; }"
        : "=r"(a) : "l"(ptr));
    return a;
}

__device__ __forceinline__ void mbar_init(uint32_t mbar, uint32_t count) {
    asm volatile("mbarrier.init.shared.b64 [%0], %1;" :: "r"(mbar), "r"(count)
                 : "memory");
}

__device__ __forceinline__ void mbar_expect_tx(uint32_t mbar, uint32_t bytes) {
    asm volatile("mbarrier.arrive.expect_tx.shared.b64 _, [%0], %1;"
                 :: "r"(mbar), "r"(bytes) : "memory");
}

__device__ __forceinline__ void bulk_g2s(uint32_t dst, const void* src,
                                         uint32_t bytes, uint32_t mbar) {
    asm volatile(
        "cp.async.bulk.shared::cta.global.mbarrier::complete_tx::bytes "
        "[%0], [%1], %2, [%3];"
        :: "r"(dst), "l"(src), "r"(bytes), "r"(mbar) : "memory");
}

__device__ __forceinline__ void mbar_wait(uint32_t mbar, uint32_t parity) {
    asm volatile(
        "{\n\t"
        ".reg .pred P;\n\t"
        "WAIT_%=:\n\t"
        "mbarrier.try_wait.parity.acquire.cta.shared::cta.b64 P, [%0], %1, 0x989680;\n\t"
        "@P bra.uni DONE_%=;\n\t"
        "bra.uni WAIT_%=;\n\t"
        "DONE_%=:\n\t"
        "}"
        :: "r"(mbar), "r"(parity) : "memory");
}

// ---------------------------------------------------------------------------
// Single fused kernel.
//   grid = (64, 32), block = (128, 2), 2 CTAs/SM.
// Phase 0: tid0 issues all 16 channel-row TMA copies (overlapped with...)
// Phase 1: per-CTA hypernetwork -> duplicated weights in smem (no global
//          round-trip, no second kernel launch).
// Phase 2: fully-unrolled 8-stage consume loop; per-warp mbar waits only,
//          all smem addresses are [reg + immediate].
//   tx -> output pairs {2tx,2tx+1} and {+256}, ty -> half of 16 out chans.
// ---------------------------------------------------------------------------
__global__ __launch_bounds__(256, 2)
void conv_kernel(const float* __restrict__ x,
                 const float* __restrict__ p,
                 const float* __restrict__ W1,
                 const float* __restrict__ b1,
                 const float* __restrict__ W2,
                 const float* __restrict__ b2,
                 float* __restrict__ y) {
    const int b   = blockIdx.y;
    const int tx  = threadIdx.x;                 // 0..127
    const int oh  = threadIdx.y;                 // 0..1
    const int tid = oh * 128 + tx;               // 0..255

    __shared__ __align__(16) unsigned long long xs[IN_CH][ROW_P];
    __shared__ __align__(16) float2 wsf[WSZ];    // duplicated weights {w,w}
    __shared__ float h[IN_CH];
    __shared__ __align__(8) unsigned long long mbar_store[NST];

    // ---- Phase 0: stage all x rows via TMA (overlaps hypernet below) ----
    const uint32_t mbar0 = smem_u32(&mbar_store[0]);
    const float* xbase = x + (size_t)(b * IN_CH) * T_IN + blockIdx.x * TILE_T;
    if (tid == 0) {
#pragma unroll
        for (int s = 0; s < NST; s++) {
            const uint32_t mb = mbar0 + 8u * s;
            mbar_init(mb, 1);
            mbar_expect_tx(mb, CPS * ROW_BYTES);
#pragma unroll
            for (int r = 0; r < CPS; r++)
                bulk_g2s(smem_u32(&xs[s * CPS + r][0]),
                         xbase + (size_t)(s * CPS + r) * T_IN, ROW_BYTES, mb);
        }
    }

    // ---- Phase 1: hypernetwork into smem weights ----
    if (tid < IN_CH) {
        float s = b1[tid];
#pragma unroll
        for (int k = 0; k < COND; k++)
            s += p[b * COND + k] * W1[k * IN_CH + tid];
        h[tid] = (s > 0.0f) ? s : 0.2f * s;
    }
    __syncthreads();

#pragma unroll
    for (int k = 0; k < 3; k++) {
        const int j = tid + 256 * k;             // 0..767
        float s = b2[j];
#pragma unroll
        for (int c = 0; c < IN_CH; c++)
            s += h[c] * W2[c * WSZ + j];
        wsf[j] = make_float2(s, s);
    }
    __syncthreads();                             // ws + mbars visible to all

    // ---- Phase 2: consume ----
    const ulonglong2* ws = reinterpret_cast<const ulonglong2*>(wsf);

    // acc[g][pp][op]: 2 groups x 2 consecutive pairs x 8 outs
    unsigned long long acc[2][2][8];
#pragma unroll
    for (int g = 0; g < 2; g++)
#pragma unroll
        for (int pp = 0; pp < 2; pp++)
#pragma unroll
            for (int op = 0; op < 8; op++)
                acc[g][pp][op] = 0ULL;

#pragma unroll
    for (int s = 0; s < NST; s++) {
        mbar_wait(mbar0 + 8u * s, 0);            // per-warp, once, parity 0

#pragma unroll
        for (int cc = 0; cc < CPS; cc++) {
            const int c = s * CPS + cc;          // compile-time constant

            // groups g at pairs 2tx+256g: taps need u64 [q..q+5] =
            // 3 contiguous ulonglong2 (conflict-free LDS.128, imm offsets).
            const ulonglong2* xr2 =
                reinterpret_cast<const ulonglong2*>(&xs[c][0]) + tx;
            ulonglong2 v[2][3];
#pragma unroll
            for (int g = 0; g < 2; g++)
#pragma unroll
                for (int k = 0; k < 3; k++)
                    v[g][k] = xr2[128 * g + k];

            const ulonglong2* wrow = ws + (c * OUT_CH + oh * 8) / 2;
            // tap i uses v[g][2-i]: .x for pair pp=0, .y for pp=1
#pragma unroll
            for (int i = 0; i < 3; i++) {
                const ulonglong2* wt = wrow + i * (IN_CH * OUT_CH / 2);
#pragma unroll
                for (int m = 0; m < 4; m++) {
                    const ulonglong2 w = wt[m];  // broadcast LDS.128
#pragma unroll
                    for (int g = 0; g < 2; g++) {
                        fma2(acc[g][0][2 * m + 0], v[g][2 - i].x, w.x);
                        fma2(acc[g][0][2 * m + 1], v[g][2 - i].x, w.y);
                        fma2(acc[g][1][2 * m + 0], v[g][2 - i].y, w.x);
                        fma2(acc[g][1][2 * m + 1], v[g][2 - i].y, w.y);
                    }
                }
            }
        }
    }

    // Store: one STG.128 per (op, group), coalesced.
    const int pbase = blockIdx.x * TILE_P + 2 * tx;
    float* ybase = y + (size_t)(b * OUT_CH + oh * 8) * T_OUT;
#pragma unroll
    for (int op = 0; op < 8; op++) {
        ulonglong2* yo = reinterpret_cast<ulonglong2*>(
            ybase + (size_t)op * T_OUT + 2 * pbase);
#pragma unroll
        for (int g = 0; g < 2; g++) {
            ulonglong2 out;
            out.x = acc[g][0][op];
            out.y = acc[g][1][op];
            yo[g * 128] = out;                   // +256 pairs = +128 u64x2
        }
    }
}

// ---------------------------------------------------------------------------
extern "C" void kernel_launch(void* const* d_in, const int* in_sizes, int n_in,
                              void* d_out, int out_size) {
    const float* x  = (const float*)d_in[0];
    const float* p  = (const float*)d_in[1];
    const float* W1 = (const float*)d_in[2];
    const float* b1 = (const float*)d_in[3];
    const float* W2 = (const float*)d_in[4];
    const float* b2 = (const float*)d_in[5];
    float* y = (float*)d_out;

    dim3 grid(T_OUT / TILE_T, B_);
    dim3 block(128, 2);
    conv_kernel<<<grid, block>>>(x, p, W1, b1, W2, b2, y);
}

// round 13
// speedup vs baseline: 2.7769x; 1.3956x over previous
#include <cuda_runtime.h>
#include <cuda_bf16.h>
#include <cstdint>

// Problem constants
#define B_     32
#define IN_CH  16
#define OUT_CH 16
#define COND   8
#define T_OUT  65536
#define T_IN   65544              // T_OUT + 8 pad
#define WSZ    768                // 48 * 16 weights per batch

// Tiling: CTA = one batch x 1024 timesteps; 8 warps x 16 eight-t tiles.
#define CTA_T    1024
#define ROWF     1032             // floats staged per channel row (1024 + 8)
#define ROW_BYTES (ROWF * 4)      // 4128, multiple of 16
#define NCHUNK   6                // K = 48 = 6 chunks of k8

// ---------------------------------------------------------------------------
// PTX helpers
// ---------------------------------------------------------------------------
__device__ __forceinline__ uint32_t smem_u32(const void* p) {
    uint32_t a;
    asm("{ .reg .u64 t; cvta.to.shared.u64 t, %1; cvt.u32.u64 %0, t; }"
        : "=r"(a) : "l"(p));
    return a;
}
__device__ __forceinline__ void mbar_init(uint32_t mb, uint32_t cnt) {
    asm volatile("mbarrier.init.shared.b64 [%0], %1;" :: "r"(mb), "r"(cnt) : "memory");
}
__device__ __forceinline__ void mbar_expect_tx(uint32_t mb, uint32_t bytes) {
    asm volatile("mbarrier.arrive.expect_tx.shared.b64 _, [%0], %1;"
                 :: "r"(mb), "r"(bytes) : "memory");
}
__device__ __forceinline__ void bulk_g2s(uint32_t dst, const void* src,
                                         uint32_t bytes, uint32_t mb) {
    asm volatile("cp.async.bulk.shared::cta.global.mbarrier::complete_tx::bytes "
                 "[%0], [%1], %2, [%3];"
                 :: "r"(dst), "l"(src), "r"(bytes), "r"(mb) : "memory");
}
__device__ __forceinline__ void mbar_wait(uint32_t mb, uint32_t parity) {
    asm volatile(
        "{\n\t.reg .pred P;\n\t"
        "W_%=:\n\t"
        "mbarrier.try_wait.parity.acquire.cta.shared::cta.b64 P, [%0], %1, 0x989680;\n\t"
        "@P bra.uni D_%=;\n\tbra.uni W_%=;\n\tD_%=:\n\t}"
        :: "r"(mb), "r"(parity) : "memory");
}
__device__ __forceinline__ uint32_t f2tf32(float v) {
    uint32_t r;
    asm("cvt.rna.tf32.f32 %0, %1;" : "=r"(r) : "f"(v));
    return r;
}

// m16n8k8 tf32 MMA: D(16x8 f32) += A(16x8 tf32, row) * B(8x8 tf32, col)
__device__ __forceinline__ void mma_tf32(float& c0, float& c1, float& c2, float& c3,
                                         uint32_t a0, uint32_t a1, uint32_t a2, uint32_t a3,
                                         uint32_t b0, uint32_t b1) {
    asm volatile(
        "mma.sync.aligned.m16n8k8.row.col.f32.tf32.tf32.f32 "
        "{%0,%1,%2,%3}, {%4,%5,%6,%7}, {%8,%9}, {%0,%1,%2,%3};"
        : "+f"(c0), "+f"(c1), "+f"(c2), "+f"(c3)
        : "r"(a0), "r"(a1), "r"(a2), "r"(a3), "r"(b0), "r"(b1));
}

// ---------------------------------------------------------------------------
// Fused kernel: hypernet + tf32 mma.sync conv.
//   grid = (64, 32), block = 256, 3 CTAs/SM.
// A = per-batch weights w[k][o] (m=16 outs, row-major), resident in 24 regs.
// B = im2col of TMA-staged x (k=48, n=8 timesteps), conflict-free LDS.32.
// Each warp: 16 tiles of 8 timesteps; 6 chained MMAs per tile; STG.64 out.
// ---------------------------------------------------------------------------
__global__ __launch_bounds__(256, 3)
void conv_kernel(const float* __restrict__ x,
                 const float* __restrict__ p,
                 const float* __restrict__ W1,
                 const float* __restrict__ b1,
                 const float* __restrict__ W2,
                 const float* __restrict__ b2,
                 float* __restrict__ y) {
    const int b    = blockIdx.y;
    const int tid  = threadIdx.x;                // 0..255
    const int warp = tid >> 5;                   // 0..7
    const int lane = tid & 31;
    const int row  = lane >> 2;                  // fragment group id (0..7)
    const int kq   = lane & 3;                   // k index within quad

    __shared__ __align__(16) float xs[IN_CH][ROWF];   // 66 KB staged x tile
    __shared__ float wsf[WSZ];                        // w[k*16+o]
    __shared__ float h[IN_CH];
    __shared__ __align__(8) unsigned long long mbars[1];

    const uint32_t mbar0 = smem_u32(&mbars[0]);

    // ---- Stage x via cp.async.bulk (overlaps hypernet) ----
    if (tid == 0) {
        mbar_init(mbar0, 1);
        mbar_expect_tx(mbar0, IN_CH * ROW_BYTES);
        const float* xb = x + (size_t)(b * IN_CH) * T_IN + blockIdx.x * CTA_T;
#pragma unroll
        for (int c = 0; c < IN_CH; c++)
            bulk_g2s(smem_u32(&xs[c][0]), xb + (size_t)c * T_IN, ROW_BYTES, mbar0);
    }

    // ---- Hypernet stage 1: h = leakyrelu(p@W1 + b1) ----
    if (tid < IN_CH) {
        float s = b1[tid];
#pragma unroll
        for (int k = 0; k < COND; k++)
            s += p[b * COND + k] * W1[k * IN_CH + tid];
        h[tid] = (s > 0.0f) ? s : 0.2f * s;
    }
    __syncthreads();

    // ---- Hypernet stage 2: w = h@W2 + b2 (j = k*16 + o) ----
#pragma unroll
    for (int it = 0; it < 3; it++) {
        const int j = tid + 256 * it;
        float s = b2[j];
#pragma unroll
        for (int c = 0; c < IN_CH; c++)
            s += h[c] * W2[c * WSZ + j];
        wsf[j] = s;
    }
    __syncthreads();

    // ---- Load resident A fragments (weights), tf32 ----
    // chunk kc: k = kc*8 + kq (+4); A row = o, col = k
    uint32_t af[NCHUNK][4];
#pragma unroll
    for (int kc = 0; kc < NCHUNK; kc++) {
        const int k0 = kc * 8 + kq;
        af[kc][0] = f2tf32(wsf[k0 * 16 + row]);
        af[kc][1] = f2tf32(wsf[k0 * 16 + row + 8]);
        af[kc][2] = f2tf32(wsf[(k0 + 4) * 16 + row]);
        af[kc][3] = f2tf32(wsf[(k0 + 4) * 16 + row + 8]);
    }

    // ---- Wait for x tile (per-warp, once) ----
    mbar_wait(mbar0, 0);

    // Per-chunk x source rows: c = (kc&1)*8 + kq (+4), tap = kc/2.
    // B col n = t within tile = lane>>2 (== row). Tap i reads t + 8 - 4i.
    const int tgbase = blockIdx.x * CTA_T;
    float* yb0 = y + (size_t)(b * OUT_CH + row) * T_OUT;
    float* yb1 = y + (size_t)(b * OUT_CH + row + 8) * T_OUT;

#pragma unroll 1
    for (int it = 0; it < 16; it++) {
        const int t0 = (it * 8 + warp) * 8;      // tile's first timestep

        float c0 = 0.f, c1 = 0.f, c2 = 0.f, c3 = 0.f;
#pragma unroll
        for (int kc = 0; kc < NCHUNK; kc++) {
            const int tap = kc >> 1;
            const int cb  = (kc & 1) * 8 + kq;
            const int u   = t0 + row + 8 - 4 * tap;   // row == lane>>2 == n
            const uint32_t b0 = f2tf32(xs[cb][u]);
            const uint32_t b1f = f2tf32(xs[cb + 4][u]);
            mma_tf32(c0, c1, c2, c3,
                     af[kc][0], af[kc][1], af[kc][2], af[kc][3], b0, b1f);
        }

        // C: thread holds (o=row, t=t0+2kq+{0,1}) and (o=row+8, same t)
        const int tg = tgbase + t0 + 2 * kq;
        *reinterpret_cast<float2*>(yb0 + tg) = make_float2(c0, c1);
        *reinterpret_cast<float2*>(yb1 + tg) = make_float2(c2, c3);
    }
}

// ---------------------------------------------------------------------------
extern "C" void kernel_launch(void* const* d_in, const int* in_sizes, int n_in,
                              void* d_out, int out_size) {
    const float* x  = (const float*)d_in[0];
    const float* p  = (const float*)d_in[1];
    const float* W1 = (const float*)d_in[2];
    const float* b1 = (const float*)d_in[3];
    const float* W2 = (const float*)d_in[4];
    const float* b2 = (const float*)d_in[5];
    float* y = (float*)d_out;

    dim3 grid(T_OUT / CTA_T, B_);
    conv_kernel<<<grid, 256>>>(x, p, W1, b1, W2, b2, y);
}

// round 14
// speedup vs baseline: 2.8862x; 1.0393x over previous
#include <cuda_runtime.h>
#include <cuda_bf16.h>
#include <cstdint>

// Problem constants
#define B_     32
#define IN_CH  16
#define OUT_CH 16
#define COND   8
#define T_OUT  65536
#define T_IN   65544              // T_OUT + 8 pad
#define WSZ    768                // 48 * 16 weights per batch

// Tiling: CTA = one batch x 1024 timesteps; 8 warps x 16 eight-t tiles.
#define CTA_T    1024
#define ROWF     1032             // floats staged per channel row (1024 + 8)
#define ROW_BYTES (ROWF * 4)      // 4128, multiple of 16
#define NCHUNK   6                // K = 48 = 6 chunks of k8

// ---------------------------------------------------------------------------
// PTX helpers
// ---------------------------------------------------------------------------
__device__ __forceinline__ uint32_t smem_u32(const void* p) {
    uint32_t a;
    asm("{ .reg .u64 t; cvta.to.shared.u64 t, %1; cvt.u32.u64 %0, t; }"
        : "=r"(a) : "l"(p));
    return a;
}
__device__ __forceinline__ void mbar_init(uint32_t mb, uint32_t cnt) {
    asm volatile("mbarrier.init.shared.b64 [%0], %1;" :: "r"(mb), "r"(cnt) : "memory");
}
__device__ __forceinline__ void mbar_expect_tx(uint32_t mb, uint32_t bytes) {
    asm volatile("mbarrier.arrive.expect_tx.shared.b64 _, [%0], %1;"
                 :: "r"(mb), "r"(bytes) : "memory");
}
__device__ __forceinline__ void bulk_g2s(uint32_t dst, const void* src,
                                         uint32_t bytes, uint32_t mb) {
    asm volatile("cp.async.bulk.shared::cta.global.mbarrier::complete_tx::bytes "
                 "[%0], [%1], %2, [%3];"
                 :: "r"(dst), "l"(src), "r"(bytes), "r"(mb) : "memory");
}
__device__ __forceinline__ void mbar_wait(uint32_t mb, uint32_t parity) {
    asm volatile(
        "{\n\t.reg .pred P;\n\t"
        "W_%=:\n\t"
        "mbarrier.try_wait.parity.acquire.cta.shared::cta.b64 P, [%0], %1, 0x989680;\n\t"
        "@P bra.uni D_%=;\n\tbra.uni W_%=;\n\tD_%=:\n\t}"
        :: "r"(mb), "r"(parity) : "memory");
}
__device__ __forceinline__ uint32_t f2tf32(float v) {
    uint32_t r;
    asm("cvt.rna.tf32.f32 %0, %1;" : "=r"(r) : "f"(v));
    return r;
}

// m16n8k8 tf32 MMA: D(16x8 f32) += A(16x8 tf32, row) * B(8x8 tf32, col)
__device__ __forceinline__ void mma_tf32(float& c0, float& c1, float& c2, float& c3,
                                         uint32_t a0, uint32_t a1, uint32_t a2, uint32_t a3,
                                         uint32_t b0, uint32_t b1) {
    asm volatile(
        "mma.sync.aligned.m16n8k8.row.col.f32.tf32.tf32.f32 "
        "{%0,%1,%2,%3}, {%4,%5,%6,%7}, {%8,%9}, {%0,%1,%2,%3};"
        : "+f"(c0), "+f"(c1), "+f"(c2), "+f"(c3)
        : "r"(a0), "r"(a1), "r"(a2), "r"(a3), "r"(b0), "r"(b1));
}

// ---------------------------------------------------------------------------
// Fused kernel: hypernet + tf32 mma.sync conv.
//   grid = (64, 32), block = 256, 3 CTAs/SM.
// A = per-batch weights w[k][o] (m=16 outs, row-major), resident in 24 regs.
// B = im2col of TMA-staged x (k=48, n=8 timesteps), conflict-free LDS.32.
// Per tile: all 12 B operands loaded+converted upfront, then TWO independent
// 3-MMA chains (even/odd chunks) merged by 8 FADDs -> MMA ILP 2.
// ---------------------------------------------------------------------------
__global__ __launch_bounds__(256, 3)
void conv_kernel(const float* __restrict__ x,
                 const float* __restrict__ p,
                 const float* __restrict__ W1,
                 const float* __restrict__ b1,
                 const float* __restrict__ W2,
                 const float* __restrict__ b2,
                 float* __restrict__ y) {
    const int b    = blockIdx.y;
    const int tid  = threadIdx.x;                // 0..255
    const int warp = tid >> 5;                   // 0..7
    const int lane = tid & 31;
    const int row  = lane >> 2;                  // fragment group id (0..7)
    const int kq   = lane & 3;                   // k index within quad

    __shared__ __align__(16) float xs[IN_CH][ROWF];   // 66 KB staged x tile
    __shared__ float wsf[WSZ];                        // w[k*16+o]
    __shared__ float h[IN_CH];
    __shared__ __align__(8) unsigned long long mbars[1];

    const uint32_t mbar0 = smem_u32(&mbars[0]);

    // ---- Stage x via cp.async.bulk (overlaps hypernet) ----
    if (tid == 0) {
        mbar_init(mbar0, 1);
        mbar_expect_tx(mbar0, IN_CH * ROW_BYTES);
        const float* xb = x + (size_t)(b * IN_CH) * T_IN + blockIdx.x * CTA_T;
#pragma unroll
        for (int c = 0; c < IN_CH; c++)
            bulk_g2s(smem_u32(&xs[c][0]), xb + (size_t)c * T_IN, ROW_BYTES, mbar0);
    }

    // ---- Hypernet stage 1: h = leakyrelu(p@W1 + b1) ----
    if (tid < IN_CH) {
        float s = b1[tid];
#pragma unroll
        for (int k = 0; k < COND; k++)
            s += p[b * COND + k] * W1[k * IN_CH + tid];
        h[tid] = (s > 0.0f) ? s : 0.2f * s;
    }
    __syncthreads();

    // ---- Hypernet stage 2: w = h@W2 + b2 (j = k*16 + o) ----
#pragma unroll
    for (int it = 0; it < 3; it++) {
        const int j = tid + 256 * it;
        float s = b2[j];
#pragma unroll
        for (int c = 0; c < IN_CH; c++)
            s += h[c] * W2[c * WSZ + j];
        wsf[j] = s;
    }
    __syncthreads();

    // ---- Load resident A fragments (weights), tf32 ----
    uint32_t af[NCHUNK][4];
#pragma unroll
    for (int kc = 0; kc < NCHUNK; kc++) {
        const int k0 = kc * 8 + kq;
        af[kc][0] = f2tf32(wsf[k0 * 16 + row]);
        af[kc][1] = f2tf32(wsf[k0 * 16 + row + 8]);
        af[kc][2] = f2tf32(wsf[(k0 + 4) * 16 + row]);
        af[kc][3] = f2tf32(wsf[(k0 + 4) * 16 + row + 8]);
    }

    // ---- Wait for x tile (per-warp, once) ----
    mbar_wait(mbar0, 0);

    const int tgbase = blockIdx.x * CTA_T;
    float* yb0 = y + (size_t)(b * OUT_CH + row) * T_OUT;
    float* yb1 = y + (size_t)(b * OUT_CH + row + 8) * T_OUT;

#pragma unroll 1
    for (int it = 0; it < 16; it++) {
        const int t0 = (it * 8 + warp) * 8;      // tile's first timestep

        // ---- Hoist all 12 B operands (LDS.32 + cvt), independent ----
        uint32_t bf[NCHUNK][2];
#pragma unroll
        for (int kc = 0; kc < NCHUNK; kc++) {
            const int tap = kc >> 1;
            const int cb  = (kc & 1) * 8 + kq;
            const int u   = t0 + row + 8 - 4 * tap;
            bf[kc][0] = f2tf32(xs[cb][u]);
            bf[kc][1] = f2tf32(xs[cb + 4][u]);
        }

        // ---- Two independent 3-MMA chains ----
        float a0 = 0.f, a1 = 0.f, a2 = 0.f, a3 = 0.f;   // chunks 0,2,4
        float e0 = 0.f, e1 = 0.f, e2 = 0.f, e3 = 0.f;   // chunks 1,3,5
#pragma unroll
        for (int s = 0; s < 3; s++) {
            mma_tf32(a0, a1, a2, a3,
                     af[2 * s][0], af[2 * s][1], af[2 * s][2], af[2 * s][3],
                     bf[2 * s][0], bf[2 * s][1]);
            mma_tf32(e0, e1, e2, e3,
                     af[2 * s + 1][0], af[2 * s + 1][1],
                     af[2 * s + 1][2], af[2 * s + 1][3],
                     bf[2 * s + 1][0], bf[2 * s + 1][1]);
        }

        // ---- Merge + store (o=row and o=row+8, t = t0+2kq+{0,1}) ----
        const int tg = tgbase + t0 + 2 * kq;
        *reinterpret_cast<float2*>(yb0 + tg) = make_float2(a0 + e0, a1 + e1);
        *reinterpret_cast<float2*>(yb1 + tg) = make_float2(a2 + e2, a3 + e3);
    }
}

// ---------------------------------------------------------------------------
extern "C" void kernel_launch(void* const* d_in, const int* in_sizes, int n_in,
                              void* d_out, int out_size) {
    const float* x  = (const float*)d_in[0];
    const float* p  = (const float*)d_in[1];
    const float* W1 = (const float*)d_in[2];
    const float* b1 = (const float*)d_in[3];
    const float* W2 = (const float*)d_in[4];
    const float* b2 = (const float*)d_in[5];
    float* y = (float*)d_out;

    dim3 grid(T_OUT / CTA_T, B_);
    conv_kernel<<<grid, 256>>>(x, p, W1, b1, W2, b2, y);
}

// round 15
// speedup vs baseline: 3.1225x; 1.0819x over previous
#include <cuda_runtime.h>
#include <cuda_bf16.h>
#include <cstdint>

// Problem constants
#define B_     32
#define IN_CH  16
#define OUT_CH 16
#define COND   8
#define T_OUT  65536
#define T_IN   65544              // T_OUT + 8 pad
#define WSZ    768                // 48 * 16 weights per batch

// Tiling: CTA = one batch x 512 timesteps; 8 warps x 8 eight-t tiles.
#define CTA_T    512
#define ROWF     520              // floats staged per channel row (512 + 8)
#define ROW_BYTES (ROWF * 4)      // 2080, multiple of 16
#define NCHUNK   6                // K = 48 = 6 chunks of k8

// Per-batch hypernet weights, tf32-pre-rounded fp32. w[b][k*16+o].
__device__ float g_w[B_ * WSZ];

// ---------------------------------------------------------------------------
// PTX helpers
// ---------------------------------------------------------------------------
__device__ __forceinline__ uint32_t smem_u32(const void* p) {
    uint32_t a;
    asm("{ .reg .u64 t; cvta.to.shared.u64 t, %1; cvt.u32.u64 %0, t; }"
        : "=r"(a) : "l"(p));
    return a;
}
__device__ __forceinline__ void mbar_init(uint32_t mb, uint32_t cnt) {
    asm volatile("mbarrier.init.shared.b64 [%0], %1;" :: "r"(mb), "r"(cnt) : "memory");
}
__device__ __forceinline__ void mbar_expect_tx(uint32_t mb, uint32_t bytes) {
    asm volatile("mbarrier.arrive.expect_tx.shared.b64 _, [%0], %1;"
                 :: "r"(mb), "r"(bytes) : "memory");
}
__device__ __forceinline__ void bulk_g2s(uint32_t dst, const void* src,
                                         uint32_t bytes, uint32_t mb) {
    asm volatile("cp.async.bulk.shared::cta.global.mbarrier::complete_tx::bytes "
                 "[%0], [%1], %2, [%3];"
                 :: "r"(dst), "l"(src), "r"(bytes), "r"(mb) : "memory");
}
__device__ __forceinline__ void mbar_wait(uint32_t mb, uint32_t parity) {
    asm volatile(
        "{\n\t.reg .pred P;\n\t"
        "W_%=:\n\t"
        "mbarrier.try_wait.parity.acquire.cta.shared::cta.b64 P, [%0], %1, 0x989680;\n\t"
        "@P bra.uni D_%=;\n\tbra.uni W_%=;\n\tD_%=:\n\t}"
        :: "r"(mb), "r"(parity) : "memory");
}
__device__ __forceinline__ uint32_t f2tf32(float v) {
    uint32_t r;
    asm("cvt.rna.tf32.f32 %0, %1;" : "=r"(r) : "f"(v));
    return r;
}

// m16n8k8 tf32 MMA: D(16x8 f32) += A(16x8 tf32, row) * B(8x8 tf32, col)
__device__ __forceinline__ void mma_tf32(float& c0, float& c1, float& c2, float& c3,
                                         uint32_t a0, uint32_t a1, uint32_t a2, uint32_t a3,
                                         uint32_t b0, uint32_t b1) {
    asm volatile(
        "mma.sync.aligned.m16n8k8.row.col.f32.tf32.tf32.f32 "
        "{%0,%1,%2,%3}, {%4,%5,%6,%7}, {%8,%9}, {%0,%1,%2,%3};"
        : "+f"(c0), "+f"(c1), "+f"(c2), "+f"(c3)
        : "r"(a0), "r"(a1), "r"(a2), "r"(a3), "r"(b0), "r"(b1));
}

// ---------------------------------------------------------------------------
// Kernel 1: hypernetwork. grid=B_, block=WSZ. Writes tf32-rounded weights.
// ---------------------------------------------------------------------------
__global__ void hyper_kernel(const float* __restrict__ p,
                             const float* __restrict__ W1,
                             const float* __restrict__ b1,
                             const float* __restrict__ W2,
                             const float* __restrict__ b2) {
    const int b = blockIdx.x;
    const int j = threadIdx.x;           // 0..767 (= k*16 + o)
    __shared__ float h[IN_CH];

    if (j < IN_CH) {
        float s = b1[j];
#pragma unroll
        for (int k = 0; k < COND; k++)
            s += p[b * COND + k] * W1[k * IN_CH + j];
        h[j] = (s > 0.0f) ? s : 0.2f * s;
    }
    __syncthreads();

    float s = b2[j];
#pragma unroll
    for (int c = 0; c < IN_CH; c++)
        s += h[c] * W2[c * WSZ + j];

    g_w[b * WSZ + j] = __uint_as_float(f2tf32(s));   // pre-rounded to tf32
}

// ---------------------------------------------------------------------------
// Kernel 2: tf32 mma.sync conv.
//   grid = (128, 32), block = 256, 4 CTAs/SM (32 warps).
// A = per-batch weights (m=16 outs, row-major, tf32 resident in 24 regs).
// B = im2col of staged x (k=48, n=8 timesteps), conflict-free LDS.32 JIT.
// Two independent 3-MMA chains merged by FADDs.
// ---------------------------------------------------------------------------
__global__ __launch_bounds__(256, 4)
void conv_kernel(const float* __restrict__ x, float* __restrict__ y) {
    const int b    = blockIdx.y;
    const int tid  = threadIdx.x;                // 0..255
    const int warp = tid >> 5;                   // 0..7
    const int lane = tid & 31;
    const int row  = lane >> 2;                  // fragment group id (0..7)
    const int kq   = lane & 3;                   // k index within quad

    __shared__ __align__(16) float xs[IN_CH][ROWF];   // 33 KB staged x tile
    __shared__ float wsf[WSZ];
    __shared__ __align__(8) unsigned long long mbars[1];

    const uint32_t mbar0 = smem_u32(&mbars[0]);

    // ---- Stage x via cp.async.bulk ----
    if (tid == 0) {
        mbar_init(mbar0, 1);
        mbar_expect_tx(mbar0, IN_CH * ROW_BYTES);
        const float* xb = x + (size_t)(b * IN_CH) * T_IN + blockIdx.x * CTA_T;
#pragma unroll
        for (int c = 0; c < IN_CH; c++)
            bulk_g2s(smem_u32(&xs[c][0]), xb + (size_t)c * T_IN, ROW_BYTES, mbar0);
    }

    // ---- Weights: 3KB from g_w (tf32-rounded already) ----
#pragma unroll
    for (int it = 0; it < 3; it++)
        wsf[tid + 256 * it] = g_w[b * WSZ + tid + 256 * it];
    __syncthreads();

    // ---- Resident A fragments ----
    uint32_t af[NCHUNK][4];
#pragma unroll
    for (int kc = 0; kc < NCHUNK; kc++) {
        const int k0 = kc * 8 + kq;
        af[kc][0] = __float_as_uint(wsf[k0 * 16 + row]);
        af[kc][1] = __float_as_uint(wsf[k0 * 16 + row + 8]);
        af[kc][2] = __float_as_uint(wsf[(k0 + 4) * 16 + row]);
        af[kc][3] = __float_as_uint(wsf[(k0 + 4) * 16 + row + 8]);
    }

    // ---- Wait for x tile (per-warp, once) ----
    mbar_wait(mbar0, 0);

    const int tgbase = blockIdx.x * CTA_T;
    float* yb0 = y + (size_t)(b * OUT_CH + row) * T_OUT;
    float* yb1 = y + (size_t)(b * OUT_CH + row + 8) * T_OUT;

#pragma unroll 1
    for (int it = 0; it < 8; it++) {
        const int t0 = (it * 8 + warp) * 8;      // tile's first timestep

        float a0 = 0.f, a1 = 0.f, a2 = 0.f, a3 = 0.f;   // chunks 0,2,4
        float e0 = 0.f, e1 = 0.f, e2 = 0.f, e3 = 0.f;   // chunks 1,3,5
#pragma unroll
        for (int s = 0; s < 3; s++) {
            // chunk 2s: tap=s, channels kq / kq+4  (u = t0 + n + 8 - 4*tap)
            {
                const int kc = 2 * s;
                const int tap = kc >> 1, cb = (kc & 1) * 8 + kq;
                const int u = t0 + row + 8 - 4 * tap;
                const uint32_t b0 = f2tf32(xs[cb][u]);
                const uint32_t b1f = f2tf32(xs[cb + 4][u]);
                mma_tf32(a0, a1, a2, a3,
                         af[kc][0], af[kc][1], af[kc][2], af[kc][3], b0, b1f);
            }
            // chunk 2s+1
            {
                const int kc = 2 * s + 1;
                const int tap = kc >> 1, cb = (kc & 1) * 8 + kq;
                const int u = t0 + row + 8 - 4 * tap;
                const uint32_t b0 = f2tf32(xs[cb][u]);
                const uint32_t b1f = f2tf32(xs[cb + 4][u]);
                mma_tf32(e0, e1, e2, e3,
                         af[kc][0], af[kc][1], af[kc][2], af[kc][3], b0, b1f);
            }
        }

        // ---- Merge + store (o=row and o=row+8, t = t0+2kq+{0,1}) ----
        const int tg = tgbase + t0 + 2 * kq;
        *reinterpret_cast<float2*>(yb0 + tg) = make_float2(a0 + e0, a1 + e1);
        *reinterpret_cast<float2*>(yb1 + tg) = make_float2(a2 + e2, a3 + e3);
    }
}

// ---------------------------------------------------------------------------
extern "C" void kernel_launch(void* const* d_in, const int* in_sizes, int n_in,
                              void* d_out, int out_size) {
    const float* x  = (const float*)d_in[0];
    const float* p  = (const float*)d_in[1];
    const float* W1 = (const float*)d_in[2];
    const float* b1 = (const float*)d_in[3];
    const float* W2 = (const float*)d_in[4];
    const float* b2 = (const float*)d_in[5];
    float* y = (float*)d_out;

    hyper_kernel<<<B_, WSZ>>>(p, W1, b1, W2, b2);

    dim3 grid(T_OUT / CTA_T, B_);
    conv_kernel<<<grid, 256>>>(x, y);
}